// round 1
// baseline (speedup 1.0000x reference)
#include <cuda_runtime.h>

// CellListComputer: cell-list build for 100k atoms, 20^3 buckets.
// Output (float32, concatenated):
//   [0,P)            within_image_pairs row0
//   [P,2P)           within_image_pairs row1
//   [2P,2P+L)        lower_between
//   [2P+L, +3n)      frac
//   [.. , +n)        imidx_from_atidx (sorted order -> atom idx)
//   [.. , +n)        atidx_from_imidx (atom idx -> sorted position)
// P, L are data-dependent; computed on device (g_P, g_L).

#define MAXN   100000
#define MAXB   8192
#define CHUNK  512
#define MAXCH  200      // ceil(100000/512) = 196 <= 200

__device__ int g_grid[3];
__device__ int g_scal[3];
__device__ int g_B;
__device__ int g_P;
__device__ int g_L;

__device__ int g_flat[MAXN];
__device__ int g_vec[MAXN];                 // packed vx | vy<<8 | vz<<16
__device__ int g_hist[MAXCH * MAXB];        // [chunk][bucket]
__device__ int g_counts[MAXB];
__device__ int g_cum[MAXB];
__device__ int g_poff[MAXB];
__device__ int g_pos[MAXN];                 // atidx_from_imidx
__device__ int g_sorted[MAXN];              // imidx_from_atidx
__device__ int g_nb[MAXN * 7];
__device__ int g_t[MAXN];
__device__ int g_aoff[MAXN];

__global__ void k_setup(const float* __restrict__ cell) {
    // bucket_length = CUTOFF/BUCKETS_PER_CUTOFF + EXTRA_SPACE (f64 -> f32)
    float bl = (float)(5.2 / 1.0 + 1e-5);
    int g0 = (int)floorf(cell[0] / bl) + 1;
    int g1 = (int)floorf(cell[4] / bl) + 1;
    int g2 = (int)floorf(cell[8] / bl) + 1;
    g_grid[0] = g0; g_grid[1] = g1; g_grid[2] = g2;
    g_B = g0 * g1 * g2;
    // NOTE: reference scaling = [grid1*grid2, grid1, 1] (replicated exactly)
    g_scal[0] = g1 * g2; g_scal[1] = g1; g_scal[2] = 1;
}

__global__ void k_zero(int total) {
    int i = blockIdx.x * blockDim.x + threadIdx.x;
    int stride = gridDim.x * blockDim.x;
    for (; i < total; i += stride) g_hist[i] = 0;
}

__global__ void k_bucket(const float* __restrict__ coord,
                         const float* __restrict__ cell, int n) {
    int i = blockIdx.x * blockDim.x + threadIdx.x;
    if (i >= n) return;
    float d0 = __ldg(cell + 0), d1 = __ldg(cell + 4), d2 = __ldg(cell + 8);
    float fx = __ldg(coord + 3 * i + 0) / d0;
    float fy = __ldg(coord + 3 * i + 1) / d1;
    float fz = __ldg(coord + 3 * i + 2) / d2;
    int vx = __float2int_rn(fx * (float)(g_grid[0] - 1));
    int vy = __float2int_rn(fy * (float)(g_grid[1] - 1));
    int vz = __float2int_rn(fz * (float)(g_grid[2] - 1));
    int flat = vx * g_scal[0] + vy * g_scal[1] + vz * g_scal[2];
    g_flat[i] = flat;
    g_vec[i] = vx | (vy << 8) | (vz << 16);
    atomicAdd(&g_hist[(i / CHUNK) * MAXB + flat], 1);
}

__global__ void k_chunkscan(int nchunks) {
    int b = blockIdx.x * blockDim.x + threadIdx.x;
    if (b >= MAXB) return;
    int run = 0;
    for (int c = 0; c < nchunks; ++c) {
        int v = g_hist[c * MAXB + b];
        g_hist[c * MAXB + b] = run;
        run += v;
    }
    g_counts[b] = run;
}

// single-block exclusive scans over buckets: cumcounts and pair offsets
__global__ void k_scanB() {
    __shared__ int sh[1024];
    int t = threadIdx.x;
    int B = g_B;
    int carry = 0;
    for (int base = 0; base < B; base += 1024) {
        int idx = base + t;
        int v = (idx < B) ? g_counts[idx] : 0;
        sh[t] = v; __syncthreads();
        for (int o = 1; o < 1024; o <<= 1) {
            int x = (t >= o) ? sh[t - o] : 0;
            __syncthreads();
            sh[t] += x; __syncthreads();
        }
        int incl = sh[t];
        int tot = sh[1023];
        __syncthreads();
        if (idx < B) g_cum[idx] = carry + incl - v;
        carry += tot;
    }
    carry = 0;
    for (int base = 0; base < B; base += 1024) {
        int idx = base + t;
        int c = (idx < B) ? g_counts[idx] : 0;
        int v = c * (c - 1) / 2;
        sh[t] = v; __syncthreads();
        for (int o = 1; o < 1024; o <<= 1) {
            int x = (t >= o) ? sh[t - o] : 0;
            __syncthreads();
            sh[t] += x; __syncthreads();
        }
        int incl = sh[t];
        int tot = sh[1023];
        __syncthreads();
        if (idx < B) g_poff[idx] = carry + incl - v;
        carry += tot;
    }
    if (t == 0) g_P = carry;
}

__global__ void k_scatter(int n) {
    __shared__ int sf[CHUNK];
    int c = blockIdx.x;
    int t = threadIdx.x;
    int i = c * CHUNK + t;
    sf[t] = (i < n) ? g_flat[i] : -1;
    __syncthreads();
    if (i >= n) return;
    int f = sf[t];
    int r = 0;
    for (int j = 0; j < t; ++j) r += (sf[j] == f);
    int pos = g_cum[f] + g_hist[c * MAXB + f] + r;
    g_pos[i] = pos;
    g_sorted[pos] = i;
}

__global__ void k_neigh(int n) {
    int i = blockIdx.x * blockDim.x + threadIdx.x;
    if (i >= n) return;
    int pk = g_vec[i];
    int vx = pk & 0xFF, vy = (pk >> 8) & 0xFF, vz = (pk >> 16) & 0xFF;
    int g0 = g_grid[0], g1 = g_grid[1], g2 = g_grid[2];
    int s0 = g_scal[0], s1 = g_scal[1];
    int tsum = 0;
    #pragma unroll
    for (int d = 0; d < 7; ++d) {
        int dx = (d >> 2) - 1;          // order: (-1,-1,-1),(-1,-1,0),...,(0,0,-1)
        int dy = ((d >> 1) & 1) - 1;
        int dz = (d & 1) - 1;
        int nx = vx + dx; if (nx < 0) nx += g0;
        int ny = vy + dy; if (ny < 0) ny += g1;
        int nz = vz + dz; if (nz < 0) nz += g2;
        int nb = nx * s0 + ny * s1 + nz;
        g_nb[7 * i + d] = nb;
        tsum += g_counts[nb];
    }
    g_t[i] = tsum;
}

__global__ void k_scanN(int n) {
    __shared__ int sh[1024];
    int t = threadIdx.x;
    int carry = 0;
    for (int base = 0; base < n; base += 1024) {
        int idx = base + t;
        int v = (idx < n) ? g_t[idx] : 0;
        sh[t] = v; __syncthreads();
        for (int o = 1; o < 1024; o <<= 1) {
            int x = (t >= o) ? sh[t - o] : 0;
            __syncthreads();
            sh[t] += x; __syncthreads();
        }
        int incl = sh[t];
        int tot = sh[1023];
        __syncthreads();
        if (idx < n) g_aoff[idx] = carry + incl - v;
        carry += tot;
    }
    if (t == 0) g_L = carry;
}

__global__ void k_pairs(float* __restrict__ out) {
    int gtid = blockIdx.x * blockDim.x + threadIdx.x;
    int wid = gtid >> 5;
    int lane = gtid & 31;
    if (wid >= g_B) return;
    int c = g_counts[wid];
    if (c < 2) return;
    int npr = c * (c - 1) / 2;
    int cum = g_cum[wid];
    int off = g_poff[wid];
    int P = g_P;
    for (int k = lane; k < npr; k += 32) {
        // enumeration: for pl=1..c-1, pu=0..pl-1; k = pl(pl-1)/2 + pu
        int pl = (int)((1.0f + sqrtf(8.0f * (float)k + 1.0f)) * 0.5f);
        while (pl * (pl - 1) / 2 > k) --pl;
        while ((pl + 1) * pl / 2 <= k) ++pl;
        int pu = k - pl * (pl - 1) / 2;
        out[off + k]     = (float)(cum + pu);
        out[P + off + k] = (float)(cum + pl);
    }
}

__global__ void k_fill(float* __restrict__ out, int n) {
    int id = blockIdx.x * blockDim.x + threadIdx.x;
    if (id >= 7 * n) return;
    int i = id / 7;
    int d = id - 7 * i;
    int base = 2 * g_P + g_aoff[i];
    #pragma unroll
    for (int d2 = 0; d2 < 6; ++d2) {
        if (d2 < d) base += g_counts[g_nb[7 * i + d2]];
    }
    int nb = g_nb[7 * i + d];
    int c = g_counts[nb];
    int cum = g_cum[nb];
    for (int j = 0; j < c; ++j) out[base + j] = (float)(cum + j);
}

__global__ void k_tail(float* __restrict__ out,
                       const float* __restrict__ coord,
                       const float* __restrict__ cell, int n) {
    int i = blockIdx.x * blockDim.x + threadIdx.x;
    if (i >= n) return;
    long long F = 2LL * g_P + g_L;
    float d0 = __ldg(cell + 0), d1 = __ldg(cell + 4), d2 = __ldg(cell + 8);
    out[F + 3LL * i + 0] = __ldg(coord + 3 * i + 0) / d0;
    out[F + 3LL * i + 1] = __ldg(coord + 3 * i + 1) / d1;
    out[F + 3LL * i + 2] = __ldg(coord + 3 * i + 2) / d2;
    out[F + 3LL * n + i] = (float)g_sorted[i];
    out[F + 4LL * n + i] = (float)g_pos[i];
}

extern "C" void kernel_launch(void* const* d_in, const int* in_sizes, int n_in,
                              void* d_out, int out_size) {
    const float* coord = (const float*)d_in[0];
    const float* cell  = (const float*)d_in[1];
    float* out = (float*)d_out;
    int n = in_sizes[0] / 3;
    int nch = (n + CHUNK - 1) / CHUNK;

    k_setup<<<1, 1>>>(cell);
    int zn = nch * MAXB;
    k_zero<<<(zn + 1023) / 1024, 1024>>>(zn);
    k_bucket<<<(n + 255) / 256, 256>>>(coord, cell, n);
    k_chunkscan<<<(MAXB + 255) / 256, 256>>>(nch);
    k_scanB<<<1, 1024>>>();
    k_scatter<<<nch, CHUNK>>>(n);
    k_neigh<<<(n + 255) / 256, 256>>>(n);
    k_scanN<<<1, 1024>>>(n);
    k_pairs<<<(MAXB * 32 + 255) / 256, 256>>>(out);
    k_fill<<<(7 * n + 255) / 256, 256>>>(out, n);
    k_tail<<<(n + 255) / 256, 256>>>(out, coord, cell, n);
}

// round 3
// speedup vs baseline: 2.9073x; 2.9073x over previous
#include <cuda_runtime.h>

// CellListComputer: cell-list build, 100k atoms, 20^3 buckets, sm_103a.
// Output layout (float32): [pairs_u | pairs_l | lower_between | frac | imidx | atidx]

#define MAXN   100000
#define MAXB   8192
#define SCHUNK 1024
#define MAXCH  104

__device__ int g_grid[3];
__device__ int g_scal[3];
__device__ int g_B;
__device__ int g_P;
__device__ int g_L;
__device__ int g_F;        // 2*P + L  (start of frac section)

__device__ int g_flat[MAXN];
__device__ int g_vec[MAXN];
__device__ int g_hist[MAXCH * MAXB];   // per-chunk counts [chunk][bucket]
__device__ int g_hoff[MAXCH * MAXB];   // per-chunk exclusive offsets
__device__ int g_counts[MAXB];
__device__ int g_cum[MAXB];
__device__ int g_poff[MAXB];
__device__ int g_pos[MAXN];
__device__ int g_sorted[MAXN];
__device__ int g_nb[MAXN * 7];
__device__ int g_aoffL[MAXN];          // block-local exclusive prefix of per-atom totals
__device__ int g_bsum[MAXCH];          // per-block totals
__device__ int g_bpre[MAXCH];          // exclusive prefix of block totals

// inclusive block scan, blockDim.x == 1024
__device__ __forceinline__ int blkscan1024(int v, int* wsum) {
    int t = threadIdx.x, lane = t & 31, w = t >> 5;
    #pragma unroll
    for (int o = 1; o < 32; o <<= 1) {
        int x = __shfl_up_sync(0xffffffffu, v, o);
        if (lane >= o) v += x;
    }
    if (lane == 31) wsum[w] = v;
    __syncthreads();
    if (w == 0) {
        int s = wsum[lane];
        #pragma unroll
        for (int o = 1; o < 32; o <<= 1) {
            int x = __shfl_up_sync(0xffffffffu, s, o);
            if (lane >= o) s += x;
        }
        wsum[lane] = s;
    }
    __syncthreads();
    int r = v + ((w > 0) ? wsum[w - 1] : 0);
    __syncthreads();
    return r;
}

// zero per-chunk histograms + compute grid params (one thread)
__global__ void k_zero(const float* __restrict__ cell, int total) {
    if (blockIdx.x == 0 && threadIdx.x == 0) {
        float bl = (float)(5.2 / 1.0 + 1e-5);
        int g0 = (int)floorf(cell[0] / bl) + 1;
        int g1 = (int)floorf(cell[4] / bl) + 1;
        int g2 = (int)floorf(cell[8] / bl) + 1;
        g_grid[0] = g0; g_grid[1] = g1; g_grid[2] = g2;
        g_B = g0 * g1 * g2;
        g_scal[0] = g1 * g2; g_scal[1] = g1; g_scal[2] = 1;
    }
    int i = blockIdx.x * blockDim.x + threadIdx.x;
    int stride = gridDim.x * blockDim.x;
    for (; i < total; i += stride) g_hist[i] = 0;
}

__global__ void k_bucket(const float* __restrict__ coord,
                         const float* __restrict__ cell, int n) {
    int i = blockIdx.x * blockDim.x + threadIdx.x;
    if (i >= n) return;
    float d0 = __ldg(cell + 0), d1 = __ldg(cell + 4), d2 = __ldg(cell + 8);
    float fx = __ldg(coord + 3 * i + 0) / d0;
    float fy = __ldg(coord + 3 * i + 1) / d1;
    float fz = __ldg(coord + 3 * i + 2) / d2;
    int vx = __float2int_rn(fx * (float)(g_grid[0] - 1));
    int vy = __float2int_rn(fy * (float)(g_grid[1] - 1));
    int vz = __float2int_rn(fz * (float)(g_grid[2] - 1));
    int flat = vx * g_scal[0] + vy * g_scal[1] + vz * g_scal[2];
    g_flat[i] = flat;
    g_vec[i] = vx | (vy << 8) | (vz << 16);
    atomicAdd(&g_hist[(i / SCHUNK) * MAXB + flat], 1);
}

// exclusive scan over chunks, per bucket. Separate in/out arrays + unroll for MLP.
__global__ void k_chunkscan(int nchunks) {
    int b = blockIdx.x * blockDim.x + threadIdx.x;
    if (b >= MAXB) return;
    int run = 0;
    int c = 0;
    for (; c + 4 <= nchunks; c += 4) {
        int v0 = g_hist[(c + 0) * MAXB + b];
        int v1 = g_hist[(c + 1) * MAXB + b];
        int v2 = g_hist[(c + 2) * MAXB + b];
        int v3 = g_hist[(c + 3) * MAXB + b];
        g_hoff[(c + 0) * MAXB + b] = run; run += v0;
        g_hoff[(c + 1) * MAXB + b] = run; run += v1;
        g_hoff[(c + 2) * MAXB + b] = run; run += v2;
        g_hoff[(c + 3) * MAXB + b] = run; run += v3;
    }
    for (; c < nchunks; ++c) {
        int v = g_hist[c * MAXB + b];
        g_hoff[c * MAXB + b] = run; run += v;
    }
    g_counts[b] = run;
}

// exclusive scans over buckets: cumcounts and pair offsets (shuffle-based)
__global__ void k_scanB() {
    __shared__ int ws[32];
    __shared__ int totC, totP;
    int t = threadIdx.x;
    int B = g_B;
    int carryC = 0, carryP = 0;
    for (int base = 0; base < B; base += 1024) {
        int idx = base + t;
        int cv = (idx < B) ? g_counts[idx] : 0;
        int pv = cv * (cv - 1) / 2;
        int ic = blkscan1024(cv, ws);
        int ip = blkscan1024(pv, ws);
        if (idx < B) {
            g_cum[idx]  = carryC + ic - cv;
            g_poff[idx] = carryP + ip - pv;
        }
        if (t == 1023) { totC = ic; totP = ip; }
        __syncthreads();
        carryC += totC; carryP += totP;
        __syncthreads();
    }
    if (t == 0) g_P = carryP;
}

// stable scatter: in-warp ranks via match_any, cross-warp via serialized smem hist
__global__ void k_scatter(int n) {
    __shared__ int hist[MAXB];
    int t = threadIdx.x;
    #pragma unroll
    for (int j = 0; j < MAXB / SCHUNK; ++j) hist[j * SCHUNK + t] = 0;
    __syncthreads();

    int i = blockIdx.x * SCHUNK + t;
    bool valid = (i < n);
    int key = valid ? g_flat[i] : 0;
    int lane = t & 31, wid = t >> 5;
    int k2 = valid ? key : (MAXB + lane);

    int rank = 0, prevcnt = 0;
    for (int w = 0; w < 32; ++w) {
        if (wid == w) {
            unsigned mm = __match_any_sync(0xffffffffu, k2);
            int leader = __ffs(mm) - 1;
            rank = __popc(mm & ((1u << lane) - 1));
            int prev = 0;
            if (lane == leader && valid) prev = atomicAdd(&hist[key], __popc(mm));
            prevcnt = __shfl_sync(0xffffffffu, prev, leader);
        }
        __syncthreads();
    }
    if (valid) {
        int pos = g_cum[key] + g_hoff[blockIdx.x * MAXB + key] + prevcnt + rank;
        g_pos[i] = pos;
        g_sorted[pos] = i;
    }
}

// neighbor buckets + per-atom totals + block-local exclusive scan
__global__ void k_neigh(int n) {
    __shared__ int ws[32];
    int i = blockIdx.x * SCHUNK + threadIdx.x;
    int tsum = 0;
    if (i < n) {
        int pk = g_vec[i];
        int vx = pk & 0xFF, vy = (pk >> 8) & 0xFF, vz = (pk >> 16) & 0xFF;
        int g0 = g_grid[0], g1 = g_grid[1], g2 = g_grid[2];
        int s0 = g_scal[0], s1 = g_scal[1];
        #pragma unroll
        for (int d = 0; d < 7; ++d) {
            int dx = (d >> 2) - 1;
            int dy = ((d >> 1) & 1) - 1;
            int dz = (d & 1) - 1;
            int nx = vx + dx; if (nx < 0) nx += g0;
            int ny = vy + dy; if (ny < 0) ny += g1;
            int nz = vz + dz; if (nz < 0) nz += g2;
            int nb = nx * s0 + ny * s1 + nz;
            g_nb[7 * i + d] = nb;
            tsum += g_counts[nb];
        }
    }
    int incl = blkscan1024(tsum, ws);
    if (i < n) g_aoffL[i] = incl - tsum;
    if (threadIdx.x == 1023) g_bsum[blockIdx.x] = incl;
}

// scan the (<=104) block totals; publish L and F = 2P + L
__global__ void k_scanC(int nch) {
    __shared__ int sm[128];
    int t = threadIdx.x;
    int v = (t < nch) ? g_bsum[t] : 0;
    sm[t] = v;
    __syncthreads();
    for (int o = 1; o < 128; o <<= 1) {
        int x = (t >= o) ? sm[t - o] : 0;
        __syncthreads();
        sm[t] += x;
        __syncthreads();
    }
    if (t < nch) g_bpre[t] = sm[t] - v;
    if (t == 127) { g_L = sm[127]; g_F = 2 * g_P + sm[127]; }
}

__global__ void k_pairs(float* __restrict__ out) {
    int gtid = blockIdx.x * blockDim.x + threadIdx.x;
    int wid = gtid >> 5;
    int lane = gtid & 31;
    if (wid >= g_B) return;
    int c = g_counts[wid];
    if (c < 2) return;
    int npr = c * (c - 1) / 2;
    int cum = g_cum[wid];
    int off = g_poff[wid];
    int P = g_P;
    for (int k = lane; k < npr; k += 32) {
        int pl = (int)((1.0f + sqrtf(8.0f * (float)k + 1.0f)) * 0.5f);
        while (pl * (pl - 1) / 2 > k) --pl;
        while ((pl + 1) * pl / 2 <= k) ++pl;
        int pu = k - pl * (pl - 1) / 2;
        out[off + k]     = (float)(cum + pu);
        out[P + off + k] = (float)(cum + pl);
    }
}

// warp per atom: coalesced lower_between fill.
// lower_between section starts at 2*P (NOT g_F — that's where frac starts).
__global__ void k_fill(float* __restrict__ out, int n) {
    __shared__ int s_start[8][8];
    __shared__ int s_cum[8][8];
    int t = threadIdx.x, wib = t >> 5, lane = t & 31;
    int w = blockIdx.x * 8 + wib;
    if (w >= n) return;
    int c = 0, cum = 0;
    if (lane < 7) {
        int nb = g_nb[7 * w + lane];
        c = g_counts[nb];
        cum = g_cum[nb];
    }
    int sc = c;
    #pragma unroll
    for (int o = 1; o < 8; o <<= 1) {
        int x = __shfl_up_sync(0xffffffffu, sc, o);
        if (lane >= o) sc += x;
    }
    if (lane < 7) { s_start[wib][lane] = sc - c; s_cum[wib][lane] = cum; }
    int total = __shfl_sync(0xffffffffu, sc, 6);
    __syncwarp();
    int base = 2 * g_P + g_aoffL[w] + g_bpre[w >> 10];
    for (int k = lane; k < total; k += 32) {
        int dd = 0;
        #pragma unroll
        for (int q = 1; q < 7; ++q)
            if (k >= s_start[wib][q]) dd = q;
        out[base + k] = (float)(s_cum[wib][dd] + k - s_start[wib][dd]);
    }
}

__global__ void k_tail(float* __restrict__ out,
                       const float* __restrict__ coord,
                       const float* __restrict__ cell, int n) {
    int i = blockIdx.x * blockDim.x + threadIdx.x;
    if (i >= n) return;
    long long F = g_F;
    float d0 = __ldg(cell + 0), d1 = __ldg(cell + 4), d2 = __ldg(cell + 8);
    out[F + 3LL * i + 0] = __ldg(coord + 3 * i + 0) / d0;
    out[F + 3LL * i + 1] = __ldg(coord + 3 * i + 1) / d1;
    out[F + 3LL * i + 2] = __ldg(coord + 3 * i + 2) / d2;
    out[F + 3LL * n + i] = (float)g_sorted[i];
    out[F + 4LL * n + i] = (float)g_pos[i];
}

extern "C" void kernel_launch(void* const* d_in, const int* in_sizes, int n_in,
                              void* d_out, int out_size) {
    const float* coord = (const float*)d_in[0];
    const float* cell  = (const float*)d_in[1];
    float* out = (float*)d_out;
    int n = in_sizes[0] / 3;
    int nch = (n + SCHUNK - 1) / SCHUNK;

    int zn = nch * MAXB;
    k_zero<<<256, 1024>>>(cell, zn);
    k_bucket<<<(n + 255) / 256, 256>>>(coord, cell, n);
    k_chunkscan<<<(MAXB + 255) / 256, 256>>>(nch);
    k_scanB<<<1, 1024>>>();
    k_scatter<<<nch, SCHUNK>>>(n);
    k_neigh<<<nch, SCHUNK>>>(n);
    k_scanC<<<1, 128>>>(nch);
    k_pairs<<<(MAXB * 32 + 255) / 256, 256>>>(out);
    k_fill<<<(n + 7) / 8, 256>>>(out, n);
    k_tail<<<(n + 255) / 256, 256>>>(out, coord, cell, n);
}

// round 5
// speedup vs baseline: 3.2000x; 1.1007x over previous
#include <cuda_runtime.h>

// CellListComputer: cell-list build, 100k atoms, 20^3 buckets, sm_103a.
// Output layout (float32): [pairs_u | pairs_l | lower_between | frac | imidx | atidx]
// 5 launches: zero+setup, bucket, chunkscan(+bucket-scan last block),
//             scatter+neigh(+chunk-total scan last block), emit(fill|pairs|tail).

#define MAXN   100000
#define MAXB   8192
#define SCHUNK 1024
#define MAXCH  104

__device__ int g_grid[3];
__device__ int g_scal[3];
__device__ int g_B;
__device__ int g_P;
__device__ int g_L;
__device__ int g_F;        // 2*P + L  (start of frac section)
__device__ unsigned g_done1, g_done2;

__device__ int g_flat[MAXN];
__device__ int g_vec[MAXN];
__device__ int g_hist[MAXCH * MAXB];   // per-chunk counts [chunk][bucket]
__device__ int g_hoff[MAXCH * MAXB];   // per-chunk exclusive offsets
__device__ __align__(16) int g_counts[MAXB];
__device__ __align__(16) int g_cum[MAXB];
__device__ __align__(16) int g_poff[MAXB];
__device__ int g_pos[MAXN];
__device__ int g_sorted[MAXN];
__device__ int g_nb[MAXN * 7];
__device__ int g_aoffL[MAXN];          // block-local exclusive prefix of per-atom totals
__device__ int g_bsum[MAXCH];          // per-block totals
__device__ int g_bpre[MAXCH];          // exclusive prefix of block totals

// inclusive block scan (int), blockDim.x == 1024
__device__ __forceinline__ int blkscan1024(int v, int* wsum) {
    int t = threadIdx.x, lane = t & 31, w = t >> 5;
    #pragma unroll
    for (int o = 1; o < 32; o <<= 1) {
        int x = __shfl_up_sync(0xffffffffu, v, o);
        if (lane >= o) v += x;
    }
    if (lane == 31) wsum[w] = v;
    __syncthreads();
    if (w == 0) {
        int s = wsum[lane];
        #pragma unroll
        for (int o = 1; o < 32; o <<= 1) {
            int x = __shfl_up_sync(0xffffffffu, s, o);
            if (lane >= o) s += x;
        }
        wsum[lane] = s;
    }
    __syncthreads();
    return v + ((w > 0) ? wsum[w - 1] : 0);
}

// inclusive block scan (u64 packed), blockDim.x == 1024
__device__ __forceinline__ unsigned long long
blkscan1024_u64(unsigned long long v, unsigned long long* wsum) {
    int t = threadIdx.x, lane = t & 31, w = t >> 5;
    #pragma unroll
    for (int o = 1; o < 32; o <<= 1) {
        unsigned long long x = __shfl_up_sync(0xffffffffu, v, o);
        if (lane >= o) v += x;
    }
    if (lane == 31) wsum[w] = v;
    __syncthreads();
    if (w == 0) {
        unsigned long long s = wsum[lane];
        #pragma unroll
        for (int o = 1; o < 32; o <<= 1) {
            unsigned long long x = __shfl_up_sync(0xffffffffu, s, o);
            if (lane >= o) s += x;
        }
        wsum[lane] = s;
    }
    __syncthreads();
    return v + ((w > 0) ? wsum[w - 1] : 0ull);
}

// zero per-chunk histograms + compute grid params + reset tickets
__global__ void k_zero(const float* __restrict__ cell, int total) {
    if (blockIdx.x == 0 && threadIdx.x == 0) {
        float bl = (float)(5.2 / 1.0 + 1e-5);
        int g0 = (int)floorf(cell[0] / bl) + 1;
        int g1 = (int)floorf(cell[4] / bl) + 1;
        int g2 = (int)floorf(cell[8] / bl) + 1;
        g_grid[0] = g0; g_grid[1] = g1; g_grid[2] = g2;
        g_B = g0 * g1 * g2;
        g_scal[0] = g1 * g2; g_scal[1] = g1; g_scal[2] = 1;
        g_done1 = 0; g_done2 = 0;
    }
    int i = blockIdx.x * blockDim.x + threadIdx.x;
    int stride = gridDim.x * blockDim.x;
    for (; i < total; i += stride) g_hist[i] = 0;
}

__global__ void k_bucket(const float* __restrict__ coord,
                         const float* __restrict__ cell, int n) {
    int i = blockIdx.x * blockDim.x + threadIdx.x;
    if (i >= n) return;
    float d0 = __ldg(cell + 0), d1 = __ldg(cell + 4), d2 = __ldg(cell + 8);
    float fx = __ldg(coord + 3 * i + 0) / d0;
    float fy = __ldg(coord + 3 * i + 1) / d1;
    float fz = __ldg(coord + 3 * i + 2) / d2;
    int vx = __float2int_rn(fx * (float)(g_grid[0] - 1));
    int vy = __float2int_rn(fy * (float)(g_grid[1] - 1));
    int vz = __float2int_rn(fz * (float)(g_grid[2] - 1));
    int flat = vx * g_scal[0] + vy * g_scal[1] + vz * g_scal[2];
    g_flat[i] = flat;
    g_vec[i] = vx | (vy << 8) | (vz << 16);
    atomicAdd(&g_hist[(i / SCHUNK) * MAXB + flat], 1);
}

// Phase 1: per-bucket exclusive scan over chunks (8 blocks x 1024, thread per bucket).
// Phase 2 (last block): single-pass scan over all 8192 buckets producing
//   g_cum (atom offsets), g_poff (pair offsets), g_P. Packed u64 scan, 8 buckets/thread.
__global__ void k_chunkscan(int nchunks) {
    int b = blockIdx.x * 1024 + threadIdx.x;
    {
        int run = 0;
        int c = 0;
        for (; c + 8 <= nchunks; c += 8) {
            int v0 = g_hist[(c + 0) * MAXB + b];
            int v1 = g_hist[(c + 1) * MAXB + b];
            int v2 = g_hist[(c + 2) * MAXB + b];
            int v3 = g_hist[(c + 3) * MAXB + b];
            int v4 = g_hist[(c + 4) * MAXB + b];
            int v5 = g_hist[(c + 5) * MAXB + b];
            int v6 = g_hist[(c + 6) * MAXB + b];
            int v7 = g_hist[(c + 7) * MAXB + b];
            g_hoff[(c + 0) * MAXB + b] = run; run += v0;
            g_hoff[(c + 1) * MAXB + b] = run; run += v1;
            g_hoff[(c + 2) * MAXB + b] = run; run += v2;
            g_hoff[(c + 3) * MAXB + b] = run; run += v3;
            g_hoff[(c + 4) * MAXB + b] = run; run += v4;
            g_hoff[(c + 5) * MAXB + b] = run; run += v5;
            g_hoff[(c + 6) * MAXB + b] = run; run += v6;
            g_hoff[(c + 7) * MAXB + b] = run; run += v7;
        }
        for (; c < nchunks; ++c) {
            int v = g_hist[c * MAXB + b];
            g_hoff[c * MAXB + b] = run; run += v;
        }
        g_counts[b] = run;
    }
    // ticket: writes -> fence -> sync -> ticket -> sync -> flag
    __threadfence();
    __syncthreads();
    __shared__ int lastflag;
    if (threadIdx.x == 0)
        lastflag = (atomicAdd(&g_done1, 1) == gridDim.x - 1);
    __syncthreads();
    if (!lastflag) return;

    // ---- bucket scan (all 1024 threads of last block present) ----
    __shared__ unsigned long long ws64[32];
    int t = threadIdx.x;
    int4 lo = __ldcg(reinterpret_cast<const int4*>(&g_counts[t * 8]));
    int4 hi = __ldcg(reinterpret_cast<const int4*>(&g_counts[t * 8 + 4]));
    int cc[8] = {lo.x, lo.y, lo.z, lo.w, hi.x, hi.y, hi.z, hi.w};
    int eC[8], eP[8];
    int sC = 0, sP = 0;
    #pragma unroll
    for (int j = 0; j < 8; ++j) {
        eC[j] = sC; sC += cc[j];
        eP[j] = sP; sP += cc[j] * (cc[j] - 1) / 2;
    }
    unsigned long long v = ((unsigned long long)(unsigned)sC << 32) | (unsigned)sP;
    unsigned long long incl = blkscan1024_u64(v, ws64);
    unsigned long long excl = incl - v;
    int baseC = (int)(excl >> 32);
    int baseP = (int)(excl & 0xffffffffull);
    int4 oc0 = make_int4(baseC + eC[0], baseC + eC[1], baseC + eC[2], baseC + eC[3]);
    int4 oc1 = make_int4(baseC + eC[4], baseC + eC[5], baseC + eC[6], baseC + eC[7]);
    int4 op0 = make_int4(baseP + eP[0], baseP + eP[1], baseP + eP[2], baseP + eP[3]);
    int4 op1 = make_int4(baseP + eP[4], baseP + eP[5], baseP + eP[6], baseP + eP[7]);
    *reinterpret_cast<int4*>(&g_cum[t * 8])      = oc0;
    *reinterpret_cast<int4*>(&g_cum[t * 8 + 4])  = oc1;
    *reinterpret_cast<int4*>(&g_poff[t * 8])     = op0;
    *reinterpret_cast<int4*>(&g_poff[t * 8 + 4]) = op1;
    if (t == 1023) g_P = (int)(incl & 0xffffffffull);
}

// scatter (stable counting-sort placement) + neighbor buckets + per-atom totals.
// Last block scans the <=104 per-block totals (single warp, no block barriers).
__global__ void k_scatneigh(int n, int nch) {
    __shared__ int hist[MAXB];
    __shared__ int ws[32];
    int t = threadIdx.x;
    #pragma unroll
    for (int j = 0; j < MAXB / SCHUNK; ++j) hist[j * SCHUNK + t] = 0;
    __syncthreads();

    int i = blockIdx.x * SCHUNK + t;
    bool valid = (i < n);
    int key = valid ? g_flat[i] : 0;
    int lane = t & 31, wid = t >> 5;
    int k2 = valid ? key : (MAXB + lane);

    int rank = 0, prevcnt = 0;
    for (int w = 0; w < 32; ++w) {
        if (wid == w) {
            unsigned mm = __match_any_sync(0xffffffffu, k2);
            int leader = __ffs(mm) - 1;
            rank = __popc(mm & ((1u << lane) - 1));
            int prev = 0;
            if (lane == leader && valid) prev = atomicAdd(&hist[key], __popc(mm));
            prevcnt = __shfl_sync(0xffffffffu, prev, leader);
        }
        __syncthreads();
    }
    if (valid) {
        int pos = g_cum[key] + g_hoff[blockIdx.x * MAXB + key] + prevcnt + rank;
        g_pos[i] = pos;
        g_sorted[pos] = i;
    }

    // neighbor buckets + per-atom totals
    int tsum = 0;
    if (valid) {
        int pk = g_vec[i];
        int vx = pk & 0xFF, vy = (pk >> 8) & 0xFF, vz = (pk >> 16) & 0xFF;
        int g0 = g_grid[0], g1 = g_grid[1], g2 = g_grid[2];
        int s0 = g_scal[0], s1 = g_scal[1];
        #pragma unroll
        for (int d = 0; d < 7; ++d) {
            int dx = (d >> 2) - 1;
            int dy = ((d >> 1) & 1) - 1;
            int dz = (d & 1) - 1;
            int nx = vx + dx; if (nx < 0) nx += g0;
            int ny = vy + dy; if (ny < 0) ny += g1;
            int nz = vz + dz; if (nz < 0) nz += g2;
            int nb = nx * s0 + ny * s1 + nz;
            g_nb[7 * i + d] = nb;
            tsum += g_counts[nb];
        }
    }
    int incl = blkscan1024(tsum, ws);
    if (valid) g_aoffL[i] = incl - tsum;
    if (t == 1023) g_bsum[blockIdx.x] = incl;

    // ticket: writes -> fence -> sync -> ticket -> sync -> flag
    __threadfence();
    __syncthreads();
    __shared__ int lastflag;
    if (t == 0) lastflag = (atomicAdd(&g_done2, 1) == gridDim.x - 1);
    __syncthreads();
    if (!lastflag) return;

    // single-warp scan of nch (<=104) block totals: 4 per lane
    if (t < 32) {
        int ex[4];
        int s = 0;
        #pragma unroll
        for (int j = 0; j < 4; ++j) {
            int idx = t * 4 + j;
            int x = (idx < nch) ? __ldcg(&g_bsum[idx]) : 0;
            ex[j] = s; s += x;
        }
        int iw = s;
        #pragma unroll
        for (int o = 1; o < 32; o <<= 1) {
            int x = __shfl_up_sync(0xffffffffu, iw, o);
            if (t >= o) iw += x;
        }
        int base = iw - s;
        #pragma unroll
        for (int j = 0; j < 4; ++j) {
            int idx = t * 4 + j;
            if (idx < nch) g_bpre[idx] = base + ex[j];
        }
        if (t == 31) { g_L = iw; g_F = 2 * g_P + iw; }
    }
}

// Fused output writer. Block ranges: [0,fillb) fill (warp per atom, 32 warps/blk),
// [fillb,fillb+pairb) pairs, rest tail. 1024 threads per block.
__global__ void k_emit(float* __restrict__ out,
                       const float* __restrict__ coord,
                       const float* __restrict__ cell,
                       int n, int fillb, int pairb) {
    int blk = blockIdx.x;
    int t = threadIdx.x;
    if (blk < fillb) {
        // ---- lower_between: warp per atom, coalesced ----
        __shared__ int s_start[32][8];
        __shared__ int s_cum[32][8];
        int wib = t >> 5, lane = t & 31;
        int w = blk * 32 + wib;
        if (w >= n) return;
        int c = 0, cum = 0;
        if (lane < 7) {
            int nb = g_nb[7 * w + lane];
            c = g_counts[nb];
            cum = g_cum[nb];
        }
        int sc = c;
        #pragma unroll
        for (int o = 1; o < 8; o <<= 1) {
            int x = __shfl_up_sync(0xffffffffu, sc, o);
            if (lane >= o) sc += x;
        }
        if (lane < 7) { s_start[wib][lane] = sc - c; s_cum[wib][lane] = cum; }
        int total = __shfl_sync(0xffffffffu, sc, 6);
        __syncwarp();
        int base = 2 * g_P + g_aoffL[w] + g_bpre[w >> 10];
        for (int k = lane; k < total; k += 32) {
            int dd = 0;
            #pragma unroll
            for (int q = 1; q < 7; ++q)
                if (k >= s_start[wib][q]) dd = q;
            out[base + k] = (float)(s_cum[wib][dd] + k - s_start[wib][dd]);
        }
    } else if (blk < fillb + pairb) {
        // ---- within-image pairs: warp per bucket ----
        int wib = t >> 5, lane = t & 31;
        int bkt = (blk - fillb) * 32 + wib;
        if (bkt >= g_B) return;
        int c = g_counts[bkt];
        if (c < 2) return;
        int npr = c * (c - 1) / 2;
        int cum = g_cum[bkt];
        int off = g_poff[bkt];
        int P = g_P;
        for (int k = lane; k < npr; k += 32) {
            int pl = (int)((1.0f + sqrtf(8.0f * (float)k + 1.0f)) * 0.5f);
            while (pl * (pl - 1) / 2 > k) --pl;
            while ((pl + 1) * pl / 2 <= k) ++pl;
            int pu = k - pl * (pl - 1) / 2;
            out[off + k]     = (float)(cum + pu);
            out[P + off + k] = (float)(cum + pl);
        }
    } else {
        // ---- frac / imidx / atidx ----
        int i = (blk - fillb - pairb) * 1024 + t;
        if (i >= n) return;
        long long F = g_F;
        float d0 = __ldg(cell + 0), d1 = __ldg(cell + 4), d2 = __ldg(cell + 8);
        out[F + 3LL * i + 0] = __ldg(coord + 3 * i + 0) / d0;
        out[F + 3LL * i + 1] = __ldg(coord + 3 * i + 1) / d1;
        out[F + 3LL * i + 2] = __ldg(coord + 3 * i + 2) / d2;
        out[F + 3LL * n + i] = (float)g_sorted[i];
        out[F + 4LL * n + i] = (float)g_pos[i];
    }
}

extern "C" void kernel_launch(void* const* d_in, const int* in_sizes, int n_in,
                              void* d_out, int out_size) {
    const float* coord = (const float*)d_in[0];
    const float* cell  = (const float*)d_in[1];
    float* out = (float*)d_out;
    int n = in_sizes[0] / 3;
    int nch = (n + SCHUNK - 1) / SCHUNK;

    int zn = nch * MAXB;
    k_zero<<<128, 1024>>>(cell, zn);
    k_bucket<<<(n + 255) / 256, 256>>>(coord, cell, n);
    k_chunkscan<<<MAXB / 1024, 1024>>>(nch);
    k_scatneigh<<<nch, SCHUNK>>>(n, nch);

    int fillb = (n + 31) / 32;          // warp per atom, 32 warps/block -> 3125 blocks
    int pairb = MAXB / 32;              // 256 blocks, warp per bucket
    int tailb = (n + 1023) / 1024;      // 98 blocks
    k_emit<<<fillb + pairb + tailb, 1024>>>(out, coord, cell, n, fillb, pairb);
}

// round 6
// speedup vs baseline: 4.0232x; 1.2573x over previous
#include <cuda_runtime.h>

// CellListComputer: cell-list build, 100k atoms, 20^3 buckets, sm_103a.
// Output layout (float32): [pairs_u | pairs_l | lower_between | frac | imidx | atidx]
// 4 launches:
//   k_init   : zero bucket counters + params
//   k_bucket : bucketize + global per-bucket atomic counts; last block: u64 scan -> cum,poff,P
//   k_place  : unstable placement via atomicAdd + neighbor lists + per-atom total scan; last: L,F
//   k_emit   : [fill (warp/atom)] [bucket warps: rank-sort + pairs + imidx/atidx] [frac]

#define MAXN   100000
#define MAXB   8192
#define MAXCH  104
#define BKTCAP 96     // smem staging capacity per bucket (max_in_bucket ~30 expected)

__device__ int g_grid[3];
__device__ int g_scal[3];
__device__ int g_B;
__device__ int g_P;
__device__ int g_L;
__device__ int g_F;          // 2*P + L (start of frac section)
__device__ unsigned g_done1, g_done2;

__device__ __align__(16) int g_counts[MAXB];
__device__ __align__(16) int g_fill[MAXB];
__device__ __align__(16) int g_cum[MAXB];
__device__ __align__(16) int g_poff[MAXB];
__device__ int g_vec[MAXN];          // packed vx | vy<<8 | vz<<16
__device__ int g_tmp[MAXN];          // unordered bucket-sliced atom indices
__device__ int g_nb[MAXN * 7];
__device__ int g_aoffL[MAXN];        // block-local exclusive prefix of per-atom totals
__device__ int g_bsum[MAXCH];
__device__ int g_bpre[MAXCH];

// inclusive block scan (int), blockDim.x == 1024
__device__ __forceinline__ int blkscan1024(int v, int* wsum) {
    int t = threadIdx.x, lane = t & 31, w = t >> 5;
    #pragma unroll
    for (int o = 1; o < 32; o <<= 1) {
        int x = __shfl_up_sync(0xffffffffu, v, o);
        if (lane >= o) v += x;
    }
    if (lane == 31) wsum[w] = v;
    __syncthreads();
    if (w == 0) {
        int s = wsum[lane];
        #pragma unroll
        for (int o = 1; o < 32; o <<= 1) {
            int x = __shfl_up_sync(0xffffffffu, s, o);
            if (lane >= o) s += x;
        }
        wsum[lane] = s;
    }
    __syncthreads();
    return v + ((w > 0) ? wsum[w - 1] : 0);
}

// inclusive block scan (u64 packed), blockDim.x == 1024
__device__ __forceinline__ unsigned long long
blkscan1024_u64(unsigned long long v, unsigned long long* wsum) {
    int t = threadIdx.x, lane = t & 31, w = t >> 5;
    #pragma unroll
    for (int o = 1; o < 32; o <<= 1) {
        unsigned long long x = __shfl_up_sync(0xffffffffu, v, o);
        if (lane >= o) v += x;
    }
    if (lane == 31) wsum[w] = v;
    __syncthreads();
    if (w == 0) {
        unsigned long long s = wsum[lane];
        #pragma unroll
        for (int o = 1; o < 32; o <<= 1) {
            unsigned long long x = __shfl_up_sync(0xffffffffu, s, o);
            if (lane >= o) s += x;
        }
        wsum[lane] = s;
    }
    __syncthreads();
    return v + ((w > 0) ? wsum[w - 1] : 0ull);
}

__global__ void k_init(const float* __restrict__ cell) {
    int t = threadIdx.x;
    if (t == 0) {
        float bl = (float)(5.2 / 1.0 + 1e-5);
        int g0 = (int)floorf(cell[0] / bl) + 1;
        int g1 = (int)floorf(cell[4] / bl) + 1;
        int g2 = (int)floorf(cell[8] / bl) + 1;
        g_grid[0] = g0; g_grid[1] = g1; g_grid[2] = g2;
        g_B = g0 * g1 * g2;
        g_scal[0] = g1 * g2; g_scal[1] = g1; g_scal[2] = 1;
        g_done1 = 0; g_done2 = 0;
    }
    #pragma unroll
    for (int j = 0; j < MAXB / 1024; ++j) {
        g_counts[j * 1024 + t] = 0;
        g_fill[j * 1024 + t] = 0;
    }
}

// bucketize + count; last-arriving block scans buckets -> g_cum, g_poff, g_P
__global__ void k_bucket(const float* __restrict__ coord,
                         const float* __restrict__ cell, int n) {
    int i = blockIdx.x * 1024 + threadIdx.x;
    if (i < n) {
        float d0 = __ldg(cell + 0), d1 = __ldg(cell + 4), d2 = __ldg(cell + 8);
        float fx = __ldg(coord + 3 * i + 0) / d0;
        float fy = __ldg(coord + 3 * i + 1) / d1;
        float fz = __ldg(coord + 3 * i + 2) / d2;
        int vx = __float2int_rn(fx * (float)(g_grid[0] - 1));
        int vy = __float2int_rn(fy * (float)(g_grid[1] - 1));
        int vz = __float2int_rn(fz * (float)(g_grid[2] - 1));
        int flat = vx * g_scal[0] + vy * g_scal[1] + vz * g_scal[2];
        g_vec[i] = vx | (vy << 8) | (vz << 16);
        atomicAdd(&g_counts[flat], 1);
    }
    __threadfence();
    __syncthreads();
    __shared__ int lastflag;
    if (threadIdx.x == 0)
        lastflag = (atomicAdd(&g_done1, 1) == gridDim.x - 1);
    __syncthreads();
    if (!lastflag) return;

    // ---- bucket scan: counts + pair-counts packed in u64, 8 buckets/thread ----
    __shared__ unsigned long long ws64[32];
    int t = threadIdx.x;
    int cc[8], eC[8], eP[8];
    #pragma unroll
    for (int j = 0; j < 8; ++j) cc[j] = __ldcg(&g_counts[t * 8 + j]);
    int sC = 0, sP = 0;
    #pragma unroll
    for (int j = 0; j < 8; ++j) {
        eC[j] = sC; sC += cc[j];
        eP[j] = sP; sP += cc[j] * (cc[j] - 1) / 2;
    }
    unsigned long long v = ((unsigned long long)(unsigned)sC << 32) | (unsigned)sP;
    unsigned long long incl = blkscan1024_u64(v, ws64);
    unsigned long long excl = incl - v;
    int baseC = (int)(excl >> 32);
    int baseP = (int)(excl & 0xffffffffull);
    int4 oc0 = make_int4(baseC + eC[0], baseC + eC[1], baseC + eC[2], baseC + eC[3]);
    int4 oc1 = make_int4(baseC + eC[4], baseC + eC[5], baseC + eC[6], baseC + eC[7]);
    int4 op0 = make_int4(baseP + eP[0], baseP + eP[1], baseP + eP[2], baseP + eP[3]);
    int4 op1 = make_int4(baseP + eP[4], baseP + eP[5], baseP + eP[6], baseP + eP[7]);
    *reinterpret_cast<int4*>(&g_cum[t * 8])      = oc0;
    *reinterpret_cast<int4*>(&g_cum[t * 8 + 4])  = oc1;
    *reinterpret_cast<int4*>(&g_poff[t * 8])     = op0;
    *reinterpret_cast<int4*>(&g_poff[t * 8 + 4]) = op1;
    if (t == 1023) g_P = (int)(incl & 0xffffffffull);
}

// unordered placement + neighbor buckets + per-atom totals; last block: L, F, bpre
__global__ void k_place(int n, int nch) {
    __shared__ int ws[32];
    int t = threadIdx.x;
    int i = blockIdx.x * 1024 + t;
    bool valid = (i < n);
    int tsum = 0;
    if (valid) {
        int pk = g_vec[i];
        int vx = pk & 0xFF, vy = (pk >> 8) & 0xFF, vz = (pk >> 16) & 0xFF;
        int g0 = g_grid[0], g1 = g_grid[1], g2 = g_grid[2];
        int s0 = g_scal[0], s1 = g_scal[1];
        int flat = vx * s0 + vy * s1 + vz;
        int slot = g_cum[flat] + atomicAdd(&g_fill[flat], 1);
        g_tmp[slot] = i;
        #pragma unroll
        for (int d = 0; d < 7; ++d) {
            int dx = (d >> 2) - 1;
            int dy = ((d >> 1) & 1) - 1;
            int dz = (d & 1) - 1;
            int nx = vx + dx; if (nx < 0) nx += g0;
            int ny = vy + dy; if (ny < 0) ny += g1;
            int nz = vz + dz; if (nz < 0) nz += g2;
            int nb = nx * s0 + ny * s1 + nz;
            g_nb[7 * i + d] = nb;
            tsum += g_counts[nb];
        }
    }
    int incl = blkscan1024(tsum, ws);
    if (valid) g_aoffL[i] = incl - tsum;
    if (t == 1023) g_bsum[blockIdx.x] = incl;

    __threadfence();
    __syncthreads();
    __shared__ int lastflag;
    if (t == 0) lastflag = (atomicAdd(&g_done2, 1) == gridDim.x - 1);
    __syncthreads();
    if (!lastflag) return;

    if (t < 32) {
        int ex[4];
        int s = 0;
        #pragma unroll
        for (int j = 0; j < 4; ++j) {
            int idx = t * 4 + j;
            int x = (idx < nch) ? __ldcg(&g_bsum[idx]) : 0;
            ex[j] = s; s += x;
        }
        int iw = s;
        #pragma unroll
        for (int o = 1; o < 32; o <<= 1) {
            int x = __shfl_up_sync(0xffffffffu, iw, o);
            if (t >= o) iw += x;
        }
        int base = iw - s;
        #pragma unroll
        for (int j = 0; j < 4; ++j) {
            int idx = t * 4 + j;
            if (idx < nch) g_bpre[idx] = base + ex[j];
        }
        if (t == 31) { g_L = iw; g_F = 2 * g_P + iw; }
    }
}

// Fused output writer. Block ranges:
//  [0,fillb): lower_between (warp per atom, 32 warps/block)
//  [fillb,fillb+bktb): warp per bucket: rank-sort -> imidx/atidx, + pairs
//  rest: frac
__global__ void k_emit(float* __restrict__ out,
                       const float* __restrict__ coord,
                       const float* __restrict__ cell,
                       int n, int fillb, int bktb) {
    int blk = blockIdx.x;
    int t = threadIdx.x;
    if (blk < fillb) {
        __shared__ int s_start[32][8];
        __shared__ int s_cum[32][8];
        int wib = t >> 5, lane = t & 31;
        int w = blk * 32 + wib;
        if (w >= n) return;
        int c = 0, cum = 0;
        if (lane < 7) {
            int nb = g_nb[7 * w + lane];
            c = g_counts[nb];
            cum = g_cum[nb];
        }
        int sc = c;
        #pragma unroll
        for (int o = 1; o < 8; o <<= 1) {
            int x = __shfl_up_sync(0xffffffffu, sc, o);
            if (lane >= o) sc += x;
        }
        if (lane < 7) { s_start[wib][lane] = sc - c; s_cum[wib][lane] = cum; }
        int total = __shfl_sync(0xffffffffu, sc, 6);
        __syncwarp();
        int base = 2 * g_P + g_aoffL[w] + g_bpre[w >> 10];
        for (int k = lane; k < total; k += 32) {
            int dd = 0;
            #pragma unroll
            for (int q = 1; q < 7; ++q)
                if (k >= s_start[wib][q]) dd = q;
            out[base + k] = (float)(s_cum[wib][dd] + k - s_start[wib][dd]);
        }
    } else if (blk < fillb + bktb) {
        // ---- warp per bucket: stable order restore + imidx/atidx + pairs ----
        __shared__ int s_val[32][BKTCAP + 1];
        int wib = t >> 5, lane = t & 31;
        int bkt = (blk - fillb) * 32 + wib;
        if (bkt >= g_B) return;
        int c = g_counts[bkt];
        int cum = g_cum[bkt];
        long long F = g_F;
        long long imb = F + 3LL * n;        // imidx base
        long long atb = F + 4LL * n;        // atidx base
        int cl = (c < BKTCAP) ? c : BKTCAP;
        for (int j = lane; j < cl; j += 32)
            s_val[wib][j] = g_tmp[cum + j];
        __syncwarp();
        for (int j = lane; j < c; j += 32) {
            int vj = (j < BKTCAP) ? s_val[wib][j] : __ldg(&g_tmp[cum + j]);
            int rank = 0;
            for (int k = 0; k < c; ++k) {
                int vk = (k < BKTCAP) ? s_val[wib][k] : __ldg(&g_tmp[cum + k]);
                rank += (vk < vj);
            }
            int slot = cum + rank;
            out[imb + slot] = (float)vj;    // imidx_from_atidx[slot] = atom
            out[atb + vj]   = (float)slot;  // atidx_from_imidx[atom] = slot
        }
        if (c < 2) return;
        int npr = c * (c - 1) / 2;
        int off = g_poff[bkt];
        int P = g_P;
        for (int k = lane; k < npr; k += 32) {
            int pl = (int)((1.0f + sqrtf(8.0f * (float)k + 1.0f)) * 0.5f);
            while (pl * (pl - 1) / 2 > k) --pl;
            while ((pl + 1) * pl / 2 <= k) ++pl;
            int pu = k - pl * (pl - 1) / 2;
            out[off + k]     = (float)(cum + pu);
            out[P + off + k] = (float)(cum + pl);
        }
    } else {
        // ---- frac ----
        int i = (blk - fillb - bktb) * 1024 + t;
        if (i >= n) return;
        long long F = g_F;
        float d0 = __ldg(cell + 0), d1 = __ldg(cell + 4), d2 = __ldg(cell + 8);
        out[F + 3LL * i + 0] = __ldg(coord + 3 * i + 0) / d0;
        out[F + 3LL * i + 1] = __ldg(coord + 3 * i + 1) / d1;
        out[F + 3LL * i + 2] = __ldg(coord + 3 * i + 2) / d2;
    }
}

extern "C" void kernel_launch(void* const* d_in, const int* in_sizes, int n_in,
                              void* d_out, int out_size) {
    const float* coord = (const float*)d_in[0];
    const float* cell  = (const float*)d_in[1];
    float* out = (float*)d_out;
    int n = in_sizes[0] / 3;
    int nblk = (n + 1023) / 1024;       // 98

    k_init<<<1, 1024>>>(cell);
    k_bucket<<<nblk, 1024>>>(coord, cell, n);
    k_place<<<nblk, 1024>>>(n, nblk);

    int fillb = (n + 31) / 32;          // 3125 blocks, warp per atom
    int bktb  = MAXB / 32;              // 256 blocks, warp per bucket
    int tailb = nblk;                   // 98 blocks, frac
    k_emit<<<fillb + bktb + tailb, 1024>>>(out, coord, cell, n, fillb, bktb);
}